// round 17
// baseline (speedup 1.0000x reference)
#include <cuda_runtime.h>
#include <cuda_fp16.h>
#include <cstdint>

// ---------------------------------------------------------------------------
// MobileMQA, all-fp16 dataflow with pre-converted operands:
// prep (W->fp16, x->x^T fp16) -> qkv conv1x1 (fp16 MMA 128x128 tiles, 3-in-1)
// -> fused dw3x3s2+GN+SiLU (smem-staged input, outputs [n][k]) -> pw1x1
// (fp16 MMA, k&v) -> GN+SiLU -> fp16 MMA flash attention (uint4 staging).
// B=32, C=256, H=W=32, heads=8, Dh=32, groups=32.
// ---------------------------------------------------------------------------

#define BATCH 32
#define CH 256
#define HW 1024
#define HWD 256
#define NH 8
#define DH 32
#define GROUPS 32
#define CPG 8
#define EPS 1e-5f

__device__ float g_scratch[33554432];   // arena, used as __half[67108864]

// offsets in halves
#define OFF_Q     0
#define OFF_KFULL 8388608
#define OFF_VFULL 16777216
#define OFF_KDS   25165824          // [b][n][k] layout
#define OFF_VDS   27262976          // [b][n][k] layout
#define OFF_KBR   29360128
#define OFF_VBR   31457280
#define OFF_XH    33554432          // x^T: [b][n=1024][k=256] fp16
#define OFF_WQH   41943040
#define OFF_WKH   42008576
#define OFF_WVH   42074112
#define OFF_KPWH  42139648
#define OFF_VPWH  42205184

__device__ __forceinline__ float fast_exp2(float x) {
    float y;
    asm("ex2.approx.ftz.f32 %0, %1;" : "=f"(y) : "f"(x));
    return y;
}

__device__ __forceinline__ uint32_t pack2h(float a, float b) {
    __half2 h = __floats2half2_rn(a, b);
    return *reinterpret_cast<uint32_t*>(&h);
}

#define MMA_F16(acc, a0,a1,a2,a3, b0,b1)                                    \
    asm volatile(                                                           \
        "mma.sync.aligned.m16n8k16.row.col.f32.f16.f16.f32 "                \
        "{%0,%1,%2,%3}, {%4,%5,%6,%7}, {%8,%9}, {%0,%1,%2,%3};"             \
        : "+f"((acc)[0]), "+f"((acc)[1]), "+f"((acc)[2]), "+f"((acc)[3])    \
        : "r"(a0), "r"(a1), "r"(a2), "r"(a3), "r"(b0), "r"(b1))

// ---------------------------------------------------------------------------
// Prep 1: convert 5 weight matrices (256x256 fp32) to fp16.
// ---------------------------------------------------------------------------
__global__ void wconv_kernel(const float* __restrict__ w0, const float* __restrict__ w1,
                             const float* __restrict__ w2, const float* __restrict__ w3,
                             const float* __restrict__ w4,
                             __half* __restrict__ o0, __half* __restrict__ o1,
                             __half* __restrict__ o2, __half* __restrict__ o3,
                             __half* __restrict__ o4)
{
    const int s = blockIdx.y;
    const float* w = s == 0 ? w0 : s == 1 ? w1 : s == 2 ? w2 : s == 3 ? w3 : w4;
    __half* o      = s == 0 ? o0 : s == 1 ? o1 : s == 2 ? o2 : s == 3 ? o3 : o4;
    int i = (blockIdx.x * 256 + threadIdx.x) * 4;
    float4 v = *reinterpret_cast<const float4*>(&w[i]);
    *reinterpret_cast<__half2*>(&o[i])     = __floats2half2_rn(v.x, v.y);
    *reinterpret_cast<__half2*>(&o[i + 2]) = __floats2half2_rn(v.z, v.w);
}

// ---------------------------------------------------------------------------
// Prep 2: transpose+convert x (B,256,1024 fp32) -> xh (B,1024,256 fp16).
// Tile 64(k) x 32(n); output rows written as full 128B uint4 runs.
// grid (HW/32, CH/64, BATCH), 256 threads.
// ---------------------------------------------------------------------------
__global__ void xpose_kernel(const float* __restrict__ x, __half* __restrict__ xh)
{
    __shared__ __half tile[64][34];
    const int n0 = blockIdx.x * 32;
    const int k0 = blockIdx.y * 64;
    const int b  = blockIdx.z;
    const float* xb = x + (size_t)b * CH * HW;
    __half* xo = xh + (size_t)b * HW * CH;
    const int t = threadIdx.x;

    // load: 64 k-rows x 32 n floats; 4 threads/row, 8 floats each (2 float4)
    {
        int kr = t >> 2;
        int nc = (t & 3) * 8;
        const float* src = &xb[(size_t)(k0 + kr) * HW + n0 + nc];
        float4 v0 = *reinterpret_cast<const float4*>(src);
        float4 v1 = *reinterpret_cast<const float4*>(src + 4);
        tile[kr][nc + 0] = __float2half(v0.x);
        tile[kr][nc + 1] = __float2half(v0.y);
        tile[kr][nc + 2] = __float2half(v0.z);
        tile[kr][nc + 3] = __float2half(v0.w);
        tile[kr][nc + 4] = __float2half(v1.x);
        tile[kr][nc + 5] = __float2half(v1.y);
        tile[kr][nc + 6] = __float2half(v1.z);
        tile[kr][nc + 7] = __float2half(v1.w);
    }
    __syncthreads();
    // store: 32 n-rows x 64 halves; 8 threads/row, one uint4 (8 halves) each
    {
        int nr = t >> 3;
        int kc = (t & 7) * 8;
        __half hv[8];
#pragma unroll
        for (int j = 0; j < 8; j++) hv[j] = tile[kc + j][nr];
        *reinterpret_cast<uint4*>(&xo[(size_t)(n0 + nr) * CH + k0 + kc]) =
            *reinterpret_cast<uint4*>(hv);
    }
}

// ---------------------------------------------------------------------------
// fp16 tensor-core GEMM, up to 3 weight sets per launch.
// Y[set][b] (fp16, [m][n]) = W[set] (fp16 [m][k]) * X[b] (fp16 [n][k]) + bias.
// grid.y: (y>>1) selects set, (y&1) selects 128-row m-tile.
// Block tile 128x128, BK=32, 256 threads (8 warps 4x2), warp tile 32x64.
// ---------------------------------------------------------------------------
#define GK 256
#define GPAD 40

__global__ void __launch_bounds__(256, 2)
gemm_f16_kernel(const __half* __restrict__ Wa, const float* __restrict__ Ba, __half* __restrict__ Ya,
                const __half* __restrict__ Wb, const float* __restrict__ Bb, __half* __restrict__ Yb,
                const __half* __restrict__ Wc, const float* __restrict__ Bc, __half* __restrict__ Yc,
                const __half* __restrict__ Xa, const __half* __restrict__ Xb2, const __half* __restrict__ Xc,
                int N)
{
    const int which = blockIdx.y >> 1;
    const __half* W   = which == 0 ? Wa : (which == 1 ? Wb : Wc);
    const float* bias = which == 0 ? Ba : (which == 1 ? Bb : Bc);
    __half* Y         = which == 0 ? Ya : (which == 1 ? Yb : Yc);
    const __half* X   = which == 0 ? Xa : (which == 1 ? Xb2 : Xc);

    const int b  = blockIdx.z;
    const int m0 = (blockIdx.y & 1) * 128;
    const int n0 = blockIdx.x * 128;

    const __half* Xb_ = X + (size_t)b * N * GK;   // [n][k]
    __half* Yo = Y + (size_t)b * 256 * N;

    __shared__ __half sA[128 * GPAD];
    __shared__ __half sB[128 * GPAD];

    const int t    = threadIdx.x;
    const int wid  = t >> 5;
    const int lane = t & 31;
    const int wm   = wid & 3;
    const int wn   = wid >> 2;
    const int g    = lane >> 2;
    const int tig  = lane & 3;

    float acc[2][8][4];
#pragma unroll
    for (int mt = 0; mt < 2; mt++)
#pragma unroll
        for (int nt = 0; nt < 8; nt++)
#pragma unroll
            for (int i = 0; i < 4; i++) acc[mt][nt][i] = 0.f;

    for (int k0 = 0; k0 < GK; k0 += 32) {
#pragma unroll
        for (int j = 0; j < 2; j++) {
            int i = t + j * 256;
            int m = i >> 2;
            int kq = i & 3;
            *reinterpret_cast<uint4*>(&sA[m * GPAD + kq * 8]) =
                *reinterpret_cast<const uint4*>(&W[(size_t)(m0 + m) * GK + k0 + kq * 8]);
            *reinterpret_cast<uint4*>(&sB[m * GPAD + kq * 8]) =
                *reinterpret_cast<const uint4*>(&Xb_[(size_t)(n0 + m) * GK + k0 + kq * 8]);
        }
        __syncthreads();

#pragma unroll
        for (int ks = 0; ks < 2; ks++) {
            const int kk = ks * 16;
            uint32_t af[2][4];
#pragma unroll
            for (int mt = 0; mt < 2; mt++) {
                int r = wm * 32 + mt * 16 + g;
                af[mt][0] = *reinterpret_cast<const uint32_t*>(&sA[r * GPAD + kk + 2 * tig]);
                af[mt][1] = *reinterpret_cast<const uint32_t*>(&sA[(r + 8) * GPAD + kk + 2 * tig]);
                af[mt][2] = *reinterpret_cast<const uint32_t*>(&sA[r * GPAD + kk + 2 * tig + 8]);
                af[mt][3] = *reinterpret_cast<const uint32_t*>(&sA[(r + 8) * GPAD + kk + 2 * tig + 8]);
            }
#pragma unroll
            for (int nt = 0; nt < 8; nt++) {
                int n = wn * 64 + nt * 8 + g;
                uint32_t b0 = *reinterpret_cast<const uint32_t*>(&sB[n * GPAD + kk + 2 * tig]);
                uint32_t b1 = *reinterpret_cast<const uint32_t*>(&sB[n * GPAD + kk + 2 * tig + 8]);
#pragma unroll
                for (int mt = 0; mt < 2; mt++)
                    MMA_F16(acc[mt][nt], af[mt][0], af[mt][1], af[mt][2], af[mt][3], b0, b1);
            }
        }
        __syncthreads();
    }

#pragma unroll
    for (int mt = 0; mt < 2; mt++) {
        int r = m0 + wm * 32 + mt * 16 + g;
        float b0 = bias ? bias[r] : 0.f;
        float b1 = bias ? bias[r + 8] : 0.f;
#pragma unroll
        for (int nt = 0; nt < 8; nt++) {
            int c = n0 + wn * 64 + nt * 8 + tig * 2;
            *reinterpret_cast<__half2*>(&Yo[(size_t)r * N + c]) =
                __floats2half2_rn(acc[mt][nt][0] + b0, acc[mt][nt][1] + b0);
            *reinterpret_cast<__half2*>(&Yo[(size_t)(r + 8) * N + c]) =
                __floats2half2_rn(acc[mt][nt][2] + b1, acc[mt][nt][3] + b1);
        }
    }
}

// ---------------------------------------------------------------------------
// Fused depthwise 3x3 s2 + GroupNorm + SiLU, fp16 I/O, k&v via blockIdx.z.
// Input tile (8 ch x 32x32 = 16 KB) smem-staged with coalesced uint4 loads.
// Output written transposed: [n=pixel][k=channel] (GEMM B format).
// grid (GROUPS, BATCH, 2), 256 threads = one output pixel each.
// ---------------------------------------------------------------------------
__global__ void dwgn_silu_kernel(const __half* __restrict__ kin, const __half* __restrict__ vin,
                                 const float* __restrict__ kdw, const float* __restrict__ vdw,
                                 const float* __restrict__ ksc, const float* __restrict__ vsc,
                                 const float* __restrict__ kbi, const float* __restrict__ vbi,
                                 __half* __restrict__ kout, __half* __restrict__ vout)
{
    const int z  = blockIdx.z;
    const __half* in = z ? vin : kin;
    const float* dw  = z ? vdw : kdw;
    const float* scale = z ? vsc : ksc;
    const float* bias  = z ? vbi : kbi;
    __half* out = z ? vout : kout;

    const int gr = blockIdx.x;
    const int b  = blockIdx.y;
    const int p  = threadIdx.x;
    const int ox = p & 15;
    const int oy = p >> 4;

    __shared__ __half sIn[CPG * HW];    // 16 KB
    const __half* ib = in + ((size_t)b * CH + gr * CPG) * HW;
#pragma unroll
    for (int j = 0; j < 4; j++) {
        int i = p + j * 256;            // uint4 index 0..1023
        reinterpret_cast<uint4*>(sIn)[i] = reinterpret_cast<const uint4*>(ib)[i];
    }
    __syncthreads();

    float vals[CPG];
    float s = 0.f, s2 = 0.f;
#pragma unroll
    for (int c = 0; c < CPG; c++) {
        const __half* sc_ = &sIn[c * HW];
        const float* wc = dw + (gr * CPG + c) * 9;
        float acc = 0.f;
#pragma unroll
        for (int ky = 0; ky < 3; ky++) {
            int iy = 2 * oy - 1 + ky;
            if ((unsigned)iy >= 32u) continue;
#pragma unroll
            for (int kx = 0; kx < 3; kx++) {
                int ix = 2 * ox - 1 + kx;
                if ((unsigned)ix >= 32u) continue;
                acc += __half2float(sc_[iy * 32 + ix]) * wc[ky * 3 + kx];
            }
        }
        vals[c] = acc;
        s += acc; s2 += acc * acc;
    }

#pragma unroll
    for (int o = 16; o > 0; o >>= 1) {
        s  += __shfl_down_sync(0xffffffffu, s,  o);
        s2 += __shfl_down_sync(0xffffffffu, s2, o);
    }
    __shared__ float rs[8], rs2[8];
    __shared__ float mu_s, rstd_s;
    int warp = p >> 5, lane = p & 31;
    if (lane == 0) { rs[warp] = s; rs2[warp] = s2; }
    __syncthreads();
    if (p == 0) {
        float S = 0.f, S2 = 0.f;
#pragma unroll
        for (int w = 0; w < 8; w++) { S += rs[w]; S2 += rs2[w]; }
        float mu  = S * (1.f / (CPG * HWD));
        float var = S2 * (1.f / (CPG * HWD)) - mu * mu;
        mu_s = mu;
        rstd_s = rsqrtf(var + EPS);
    }
    __syncthreads();
    float mu = mu_s, rstd = rstd_s;

    __half hv[CPG];
#pragma unroll
    for (int c = 0; c < CPG; c++) {
        int ch = gr * CPG + c;
        float y = (vals[c] - mu) * rstd * scale[ch] + bias[ch];
        y = y / (1.f + __expf(-y));
        hv[c] = __float2half(y);
    }
    *reinterpret_cast<uint4*>(&out[((size_t)b * HWD + p) * CH + gr * CPG]) =
        *reinterpret_cast<uint4*>(hv);
}

// ---------------------------------------------------------------------------
// GroupNorm + SiLU, fp16 in-place ([ch][pixel] layout), k&v via blockIdx.z.
// ---------------------------------------------------------------------------
__global__ void gn_silu_kernel(__half* __restrict__ kx, __half* __restrict__ vx,
                               const float* __restrict__ ksc, const float* __restrict__ vsc,
                               const float* __restrict__ kbi, const float* __restrict__ vbi)
{
    const int z = blockIdx.z;
    __half* x = z ? vx : kx;
    const float* scale = z ? vsc : ksc;
    const float* bias  = z ? vbi : kbi;

    const int g = blockIdx.x;
    const int b = blockIdx.y;
    __half* base = x + ((size_t)b * CH + g * CPG) * HWD;
    const int p = threadIdx.x;

    float vals[CPG];
    float s = 0.f, s2 = 0.f;
#pragma unroll
    for (int c = 0; c < CPG; c++) {
        float v = __half2float(base[c * HWD + p]);
        vals[c] = v;
        s += v; s2 += v * v;
    }

#pragma unroll
    for (int o = 16; o > 0; o >>= 1) {
        s  += __shfl_down_sync(0xffffffffu, s,  o);
        s2 += __shfl_down_sync(0xffffffffu, s2, o);
    }
    __shared__ float rs[8], rs2[8];
    __shared__ float mu_s, rstd_s;
    int warp = p >> 5, lane = p & 31;
    if (lane == 0) { rs[warp] = s; rs2[warp] = s2; }
    __syncthreads();
    if (p == 0) {
        float S = 0.f, S2 = 0.f;
#pragma unroll
        for (int w = 0; w < 8; w++) { S += rs[w]; S2 += rs2[w]; }
        float mu  = S * (1.f / (CPG * HWD));
        float var = S2 * (1.f / (CPG * HWD)) - mu * mu;
        mu_s = mu;
        rstd_s = rsqrtf(var + EPS);
    }
    __syncthreads();
    float mu = mu_s, rstd = rstd_s;

#pragma unroll
    for (int c = 0; c < CPG; c++) {
        int ch = g * CPG + c;
        float y = (vals[c] - mu) * rstd * scale[ch] + bias[ch];
        y = y / (1.f + __expf(-y));
        base[c * HWD + p] = __float2half(y);
    }
}

// ---------------------------------------------------------------------------
// fp16 tensor-core flash attention. Block = (b,h) x 128 queries, M=256 KV.
// Staging gmem side is uint4-vectorized; V is a straight [d][m] copy.
// ---------------------------------------------------------------------------
#define AQ 128
#define AM 256
#define QPAD 40
#define VPAD 264
#define SMEM_HALVES (AQ*QPAD + AM*QPAD + DH*VPAD)

__global__ void __launch_bounds__(256, 2)
attn_fp16_kernel(const __half* __restrict__ q,
                 const __half* __restrict__ k,
                 const __half* __restrict__ v,
                 float* __restrict__ out)
{
    __shared__ __align__(16) __half smem[SMEM_HALVES];
    __half* sQ = smem;
    __half* sK = smem + AQ * QPAD;
    __half* sV = smem + AQ * QPAD + AM * QPAD;
    float* sO = reinterpret_cast<float*>(smem);

    const int b  = blockIdx.z;
    const int h  = blockIdx.y;
    const int n0 = blockIdx.x * AQ;

    const __half* qb = q + ((size_t)b * CH + h * DH) * HW;
    const __half* kb = k + ((size_t)b * CH + h * DH) * HWD;
    const __half* vb = v + ((size_t)b * CH + h * DH) * HWD;
    float* ob = out + ((size_t)b * CH + h * DH) * HW;

    const int t    = threadIdx.x;
    const int w    = t >> 5;
    const int lane = t & 31;
    const int g    = lane >> 2;
    const int tig  = lane & 3;
    const int r0   = w * 16;

    const float qs = 0.17677669529663687f * 1.4426950408889634f;

    // ---- stage Q [n][d] (gmem [d][n], uint4 loads + scalar scatter) ----
#pragma unroll
    for (int j = 0; j < 2; j++) {
        int i = t + j * 256;           // 0..511
        int d  = i >> 4;               // 16 uint4 per d-row
        int n8 = (i & 15) * 8;
        uint4 vv = *reinterpret_cast<const uint4*>(&qb[(size_t)d * HW + n0 + n8]);
        const __half* hv = reinterpret_cast<const __half*>(&vv);
#pragma unroll
        for (int e = 0; e < 8; e++) sQ[(n8 + e) * QPAD + d] = hv[e];
    }
    // ---- stage K [m][d] (gmem [d][m], uint4 loads + scalar scatter) ----
#pragma unroll
    for (int j = 0; j < 4; j++) {
        int i = t + j * 256;           // 0..1023
        int d  = i >> 5;               // 32 uint4 per d-row
        int m8 = (i & 31) * 8;
        uint4 vv = *reinterpret_cast<const uint4*>(&kb[(size_t)d * HWD + m8]);
        const __half* hv = reinterpret_cast<const __half*>(&vv);
#pragma unroll
        for (int e = 0; e < 8; e++) sK[(m8 + e) * QPAD + d] = hv[e];
    }
    // ---- stage V [d][m]: straight vectorized copy ----
#pragma unroll
    for (int j = 0; j < 4; j++) {
        int i = t + j * 256;
        int d  = i >> 5;
        int m8 = (i & 31) * 8;
        *reinterpret_cast<uint4*>(&sV[d * VPAD + m8]) =
            *reinterpret_cast<const uint4*>(&vb[(size_t)d * HWD + m8]);
    }
    __syncthreads();

    float o[4][4];
#pragma unroll
    for (int dt = 0; dt < 4; dt++)
#pragma unroll
        for (int i = 0; i < 4; i++) o[dt][i] = 0.f;
    float mx0 = -1e30f, mx1 = -1e30f, sum0 = 0.f, sum1 = 0.f;

#pragma unroll
    for (int chunk = 0; chunk < 2; chunk++) {
        const int c0 = chunk * 128;

        float s[16][4];
#pragma unroll
        for (int nt = 0; nt < 16; nt++)
#pragma unroll
            for (int i = 0; i < 4; i++) s[nt][i] = 0.f;

#pragma unroll
        for (int ks = 0; ks < 2; ks++) {
            const int kk = ks * 16;
            uint32_t a0 = *reinterpret_cast<const uint32_t*>(&sQ[(r0 + g) * QPAD + kk + 2 * tig]);
            uint32_t a1 = *reinterpret_cast<const uint32_t*>(&sQ[(r0 + g + 8) * QPAD + kk + 2 * tig]);
            uint32_t a2 = *reinterpret_cast<const uint32_t*>(&sQ[(r0 + g) * QPAD + kk + 2 * tig + 8]);
            uint32_t a3 = *reinterpret_cast<const uint32_t*>(&sQ[(r0 + g + 8) * QPAD + kk + 2 * tig + 8]);
#pragma unroll
            for (int nt = 0; nt < 16; nt++) {
                int m = c0 + nt * 8 + g;
                uint32_t b0 = *reinterpret_cast<const uint32_t*>(&sK[m * QPAD + kk + 2 * tig]);
                uint32_t b1 = *reinterpret_cast<const uint32_t*>(&sK[m * QPAD + kk + 2 * tig + 8]);
                MMA_F16(s[nt], a0, a1, a2, a3, b0, b1);
            }
        }

#pragma unroll
        for (int nt = 0; nt < 16; nt++)
#pragma unroll
            for (int i = 0; i < 4; i++) s[nt][i] *= qs;

        float cm0 = -1e30f, cm1 = -1e30f;
#pragma unroll
        for (int nt = 0; nt < 16; nt++) {
            cm0 = fmaxf(cm0, fmaxf(s[nt][0], s[nt][1]));
            cm1 = fmaxf(cm1, fmaxf(s[nt][2], s[nt][3]));
        }
        cm0 = fmaxf(cm0, __shfl_xor_sync(0xffffffffu, cm0, 1));
        cm0 = fmaxf(cm0, __shfl_xor_sync(0xffffffffu, cm0, 2));
        cm1 = fmaxf(cm1, __shfl_xor_sync(0xffffffffu, cm1, 1));
        cm1 = fmaxf(cm1, __shfl_xor_sync(0xffffffffu, cm1, 2));

        float nm0 = fmaxf(mx0, cm0);
        float nm1 = fmaxf(mx1, cm1);
        float f0 = fast_exp2(mx0 - nm0);
        float f1 = fast_exp2(mx1 - nm1);
        sum0 *= f0; sum1 *= f1;
#pragma unroll
        for (int dt = 0; dt < 4; dt++) {
            o[dt][0] *= f0; o[dt][1] *= f0;
            o[dt][2] *= f1; o[dt][3] *= f1;
        }
        mx0 = nm0; mx1 = nm1;

#pragma unroll
        for (int mc = 0; mc < 8; mc++) {
            float p00 = fast_exp2(s[2*mc][0] - mx0);
            float p01 = fast_exp2(s[2*mc][1] - mx0);
            float p02 = fast_exp2(s[2*mc][2] - mx1);
            float p03 = fast_exp2(s[2*mc][3] - mx1);
            float p10 = fast_exp2(s[2*mc+1][0] - mx0);
            float p11 = fast_exp2(s[2*mc+1][1] - mx0);
            float p12 = fast_exp2(s[2*mc+1][2] - mx1);
            float p13 = fast_exp2(s[2*mc+1][3] - mx1);
            sum0 += p00 + p01 + p10 + p11;
            sum1 += p02 + p03 + p12 + p13;
            uint32_t a0 = pack2h(p00, p01);
            uint32_t a1 = pack2h(p02, p03);
            uint32_t a2 = pack2h(p10, p11);
            uint32_t a3 = pack2h(p12, p13);
            const int mbase = c0 + mc * 16 + 2 * tig;
#pragma unroll
            for (int dt = 0; dt < 4; dt++) {
                int dd = dt * 8 + g;
                uint32_t b0 = *reinterpret_cast<const uint32_t*>(&sV[dd * VPAD + mbase]);
                uint32_t b1 = *reinterpret_cast<const uint32_t*>(&sV[dd * VPAD + mbase + 8]);
                MMA_F16(o[dt], a0, a1, a2, a3, b0, b1);
            }
        }
    }

    sum0 += __shfl_xor_sync(0xffffffffu, sum0, 1);
    sum0 += __shfl_xor_sync(0xffffffffu, sum0, 2);
    sum1 += __shfl_xor_sync(0xffffffffu, sum1, 1);
    sum1 += __shfl_xor_sync(0xffffffffu, sum1, 2);
    float inv0 = 1.f / sum0;
    float inv1 = 1.f / sum1;

    __syncthreads();

#pragma unroll
    for (int dt = 0; dt < 4; dt++) {
        int c = dt * 8 + tig * 2;
        sO[(r0 + g) * 33 + c]     = o[dt][0] * inv0;
        sO[(r0 + g) * 33 + c + 1] = o[dt][1] * inv0;
        sO[(r0 + g + 8) * 33 + c]     = o[dt][2] * inv1;
        sO[(r0 + g + 8) * 33 + c + 1] = o[dt][3] * inv1;
    }
    __syncthreads();

    for (int i = t; i < AQ * DH; i += 256) {
        int d = i >> 7, n = i & 127;
        ob[d * HW + n0 + n] = sO[n * 33 + d];
    }
}

// ---------------------------------------------------------------------------
// Host launcher
// ---------------------------------------------------------------------------
extern "C" void kernel_launch(void* const* d_in, const int* in_sizes, int n_in,
                              void* d_out, int out_size)
{
    const float* x      = (const float*)d_in[0];
    const float* wq     = (const float*)d_in[1];
    const float* bq     = (const float*)d_in[2];
    const float* wk     = (const float*)d_in[3];
    const float* bk     = (const float*)d_in[4];
    const float* wv     = (const float*)d_in[5];
    const float* bv     = (const float*)d_in[6];
    const float* k_dw   = (const float*)d_in[7];
    const float* k_gn1s = (const float*)d_in[8];
    const float* k_gn1b = (const float*)d_in[9];
    const float* k_pw   = (const float*)d_in[10];
    const float* k_gn2s = (const float*)d_in[11];
    const float* k_gn2b = (const float*)d_in[12];
    const float* v_dw   = (const float*)d_in[13];
    const float* v_gn1s = (const float*)d_in[14];
    const float* v_gn1b = (const float*)d_in[15];
    const float* v_pw   = (const float*)d_in[16];
    const float* v_gn2s = (const float*)d_in[17];
    const float* v_gn2b = (const float*)d_in[18];
    float* out = (float*)d_out;

    float* basef = nullptr;
    cudaGetSymbolAddress((void**)&basef, g_scratch);
    __half* base = (__half*)basef;
    __half* q     = base + OFF_Q;
    __half* kfull = base + OFF_KFULL;
    __half* vfull = base + OFF_VFULL;
    __half* kds   = base + OFF_KDS;
    __half* vds   = base + OFF_VDS;
    __half* kbr   = base + OFF_KBR;
    __half* vbr   = base + OFF_VBR;
    __half* xh    = base + OFF_XH;
    __half* wqh   = base + OFF_WQH;
    __half* wkh   = base + OFF_WKH;
    __half* wvh   = base + OFF_WVH;
    __half* kpwh  = base + OFF_KPWH;
    __half* vpwh  = base + OFF_VPWH;

    // 0) prep: weights -> fp16; x -> x^T fp16
    {
        dim3 grid(64, 5);
        wconv_kernel<<<grid, 256>>>(wq, wk, wv, k_pw, v_pw,
                                    wqh, wkh, wvh, kpwh, vpwh);
        dim3 tgrid(HW / 32, CH / 64, BATCH);
        xpose_kernel<<<tgrid, 256>>>(x, xh);
    }

    // 1) q/k/v pointwise convs fused in one launch (fp16 MMA, 128x128 tiles)
    {
        dim3 grid(HW / 128, 6, BATCH);
        gemm_f16_kernel<<<grid, 256>>>(
            wqh, bq, q,  wkh, bk, kfull,  wvh, bv, vfull,
            xh, xh, xh, HW);
    }

    // 2) fused depthwise s2 + GN1 + SiLU (k & v), outputs [n][k]
    {
        dim3 grid(GROUPS, BATCH, 2);
        dwgn_silu_kernel<<<grid, HWD>>>(kfull, vfull, k_dw, v_dw,
                                        k_gn1s, v_gn1s, k_gn1b, v_gn1b,
                                        kds, vds);
    }

    // 3) pointwise convs (no bias), k & v fused (fp16 MMA)
    {
        dim3 grid(HWD / 128, 4, BATCH);
        gemm_f16_kernel<<<grid, 256>>>(
            kpwh, nullptr, kbr,  vpwh, nullptr, vbr,  kpwh, nullptr, kbr,
            kds, vds, kds, HWD);
    }

    // 4) GN2 + SiLU (k & v, in-place)
    {
        dim3 grid(GROUPS, BATCH, 2);
        gn_silu_kernel<<<grid, HWD>>>(kbr, vbr, k_gn2s, v_gn2s, k_gn2b, v_gn2b);
    }

    // 5) attention -> output (B,C,H,W) fp32
    {
        dim3 grid(HW / AQ, NH, BATCH);
        attn_fp16_kernel<<<grid, 256>>>(q, kbr, vbr, out);
    }
}